// round 2
// baseline (speedup 1.0000x reference)
#include <cuda_runtime.h>
#include <math.h>

#define LL 1024
#define BB 128
#define DD 256
#define HH 256

// Packed f32x2 FMA: d = a*b + c elementwise on 2 floats packed in 64 bits.
__device__ __forceinline__ unsigned long long ffma2(
    unsigned long long a, unsigned long long b, unsigned long long c)
{
    unsigned long long d;
    asm("fma.rn.f32x2 %0, %1, %2, %3;" : "=l"(d) : "l"(a), "l"(b), "l"(c));
    return d;
}

__device__ __forceinline__ float upk_sum(unsigned long long p)
{
    float lo, hi;
    asm("mov.b64 {%0, %1}, %2;" : "=f"(lo), "=f"(hi) : "l"(p));
    return lo + hi;
}

// =====================================================================
// Kernel 1: xproj[m, j] = sum_d X[m,d] * Wx[j,d] + bx[j],  M = L*B
// BM=128, BN=64, BK=16, 256 threads, 8x4 microtile, f32x2 packed FMA.
// A packed along M (rows contiguous in As), B pre-duplicated in smem.
// =====================================================================
__global__ __launch_bounds__(256) void xproj_kernel(
    const float* __restrict__ X,
    const float* __restrict__ Wx,
    const float* __restrict__ bx,
    float* __restrict__ C)
{
    __shared__ float  As[16][132];     // [k][m], padded; row stride 528B (16B mult)
    __shared__ float2 Bs2[16][66];     // [k][j] duplicated {b,b}; row 528B

    const int m0 = blockIdx.x * 128;
    const int n0 = blockIdx.y * 64;
    const int tid = threadIdx.x;
    const int tm = (tid >> 4) * 8;   // 0..120
    const int tn = (tid & 15) * 4;   // 0..60

    unsigned long long accp[4][4];   // [m-pair][n]
#pragma unroll
    for (int i = 0; i < 4; i++)
#pragma unroll
        for (int jj = 0; jj < 4; jj++) accp[i][jj] = 0ULL;

    for (int k0 = 0; k0 < DD; k0 += 16) {
        // load A tile: 128 rows x 16 k  (512 float4, 2 per thread)
#pragma unroll
        for (int i = 0; i < 2; i++) {
            int idx  = i * 256 + tid;
            int row  = idx >> 2;
            int col4 = idx & 3;
            float4 v = *(const float4*)(X + (size_t)(m0 + row) * DD + k0 + col4 * 4);
            As[col4 * 4 + 0][row] = v.x;
            As[col4 * 4 + 1][row] = v.y;
            As[col4 * 4 + 2][row] = v.z;
            As[col4 * 4 + 3][row] = v.w;
        }
        // load B tile: 64 rows x 16 k, store duplicated {b,b}
        {
            int row  = tid >> 2;
            int col4 = tid & 3;
            float4 v = *(const float4*)(Wx + (size_t)(n0 + row) * DD + k0 + col4 * 4);
            Bs2[col4 * 4 + 0][row] = make_float2(v.x, v.x);
            Bs2[col4 * 4 + 1][row] = make_float2(v.y, v.y);
            Bs2[col4 * 4 + 2][row] = make_float2(v.z, v.z);
            Bs2[col4 * 4 + 3][row] = make_float2(v.w, v.w);
        }
        __syncthreads();

#pragma unroll
        for (int k = 0; k < 16; k++) {
            // a: rows tm..tm+7 as 4 packed pairs (contiguous in As)
            const ulonglong2* pa = (const ulonglong2*)&As[k][tm];
            ulonglong2 A0 = pa[0], A1 = pa[1];
            unsigned long long ap[4] = { A0.x, A0.y, A1.x, A1.y };
            // b: 4 duplicated pairs, contiguous in Bs2
            const ulonglong2* pb = (const ulonglong2*)&Bs2[k][tn];
            ulonglong2 B0 = pb[0], B1 = pb[1];
            unsigned long long bd[4] = { B0.x, B0.y, B1.x, B1.y };
#pragma unroll
            for (int m = 0; m < 4; m++)
#pragma unroll
                for (int jj = 0; jj < 4; jj++)
                    accp[m][jj] = ffma2(ap[m], bd[jj], accp[m][jj]);
        }
        __syncthreads();
    }

    float4 bxv = *(const float4*)(bx + n0 + tn);
    const float bias[4] = { bxv.x, bxv.y, bxv.z, bxv.w };
#pragma unroll
    for (int m = 0; m < 4; m++) {
        float r0c[4], r1c[4];
#pragma unroll
        for (int jj = 0; jj < 4; jj++) {
            float lo, hi;
            asm("mov.b64 {%0, %1}, %2;" : "=f"(lo), "=f"(hi) : "l"(accp[m][jj]));
            r0c[jj] = lo + bias[jj];
            r1c[jj] = hi + bias[jj];
        }
        int r0 = m0 + tm + 2 * m;
        *(float4*)(C + (size_t)r0 * HH + n0 + tn)       = make_float4(r0c[0], r0c[1], r0c[2], r0c[3]);
        *(float4*)(C + (size_t)(r0 + 1) * HH + n0 + tn) = make_float4(r1c[0], r1c[1], r1c[2], r1c[3]);
    }
}

// =====================================================================
// Kernel 2: persistent scan. One CTA per batch element (128 CTAs).
// 512 threads: thread (j = tid&255, half = tid>>8) covers k in
// [half*128, half*128+128). 80 k-weights in registers, 48 in smem.
// f32x2 packed FMA along k (operands naturally contiguous).
// =====================================================================
__global__ __launch_bounds__(512, 1) void scan_kernel(
    const float* __restrict__ h0,
    const float* __restrict__ Wh,
    const float* __restrict__ bh,
    float* __restrict__ out,
    int hasFinal)
{
    extern __shared__ float smem[];
    float4* Ws4  = (float4*)smem;            // 24*256 float4 = 96 KB
    float*  hbuf = smem + 24 * 256 * 4;      // 2*256 floats (ping-pong)
    float*  part = hbuf + 512;               // 256 floats
    float*  bh_s = part + 256;               // 256 floats

    const int tid  = threadIdx.x;
    const int j    = tid & 255;
    const int half = tid >> 8;
    const int b    = blockIdx.x;
    const int kb   = half * 128;

    // register-resident weights: k in [kb, kb+80), as 40 packed pairs
    ulonglong2 wu[20];
    const ulonglong2* wrow = (const ulonglong2*)(Wh + (size_t)j * HH + kb);
#pragma unroll
    for (int i = 0; i < 20; i++) wu[i] = wrow[i];

    // shared weights: g<12 -> k = 80+4g (half 0), g>=12 -> k = 208+4(g-12) (half 1)
    for (int idx = tid; idx < 24 * 256; idx += 512) {
        int g  = idx >> 8;
        int jj = idx & 255;
        int kk = (g < 12) ? (80 + 4 * g) : (208 + 4 * (g - 12));
        Ws4[g * 256 + jj] = *(const float4*)(Wh + (size_t)jj * HH + kk);
    }
    if (tid < 256) {
        hbuf[tid] = h0[(size_t)b * HH + tid];
        bh_s[tid] = bh[tid];
    }
    __syncthreads();

    int cur = 0;
    for (int t = 0; t < LL; ++t) {
        float xp = 0.0f;
        if (!half) xp = out[(size_t)t * (BB * HH) + (size_t)b * HH + j];

        const ulonglong2* h2 = (const ulonglong2*)(hbuf + cur * 256 + kb);
        unsigned long long p0 = 0ULL, p1 = 0ULL, p2 = 0ULL, p3 = 0ULL;
#pragma unroll
        for (int i = 0; i < 20; i++) {
            ulonglong2 hv = h2[i];
            p0 = ffma2(wu[i].x, hv.x, p0);
            p1 = ffma2(wu[i].y, hv.y, p1);
        }
        const ulonglong2* ws2 = (const ulonglong2*)(Ws4 + half * 12 * 256 + j);
#pragma unroll
        for (int g = 0; g < 12; g++) {
            ulonglong2 wv = ws2[(size_t)g * 256];
            ulonglong2 hv = h2[20 + g];
            p2 = ffma2(wv.x, hv.x, p2);
            p3 = ffma2(wv.y, hv.y, p3);
        }
        float acc = (upk_sum(p0) + upk_sum(p1)) + (upk_sum(p2) + upk_sum(p3));

        if (half) part[j] = acc;
        __syncthreads();

        if (!half) {
            float v  = acc + part[j] + xp + bh_s[j];
            float hn = tanhf(v);
            hbuf[(cur ^ 1) * 256 + j] = hn;
            out[(size_t)t * (BB * HH) + (size_t)b * HH + j] = hn;
            if (hasFinal && t == LL - 1)
                out[(size_t)LL * BB * HH + (size_t)b * HH + j] = hn;
        }
        __syncthreads();
        cur ^= 1;
    }
}

// =====================================================================
// launch
// =====================================================================
extern "C" void kernel_launch(void* const* d_in, const int* in_sizes, int n_in,
                              void* d_out, int out_size)
{
    const float* x   = (const float*)d_in[0];  // [L,B,D]
    const float* h0  = (const float*)d_in[1];  // [B,H]
    const float* Wxw = (const float*)d_in[2];  // [H,D]
    const float* Wxb = (const float*)d_in[3];  // [H]
    const float* Whw = (const float*)d_in[4];  // [H,H]
    const float* Whb = (const float*)d_in[5];  // [H]
    float* out = (float*)d_out;

    (void)in_sizes; (void)n_in;

    const int smemScan = (24 * 256 * 4 + 512 + 256 + 256) * (int)sizeof(float); // 102400
    cudaFuncSetAttribute(scan_kernel, cudaFuncAttributeMaxDynamicSharedMemorySize, smemScan);

    dim3 g1(LL * BB / 128, HH / 64);   // (1024, 4)
    xproj_kernel<<<g1, 256>>>(x, Wxw, Wxb, out);

    const int hasFinal = (out_size >= LL * BB * HH + BB * HH) ? 1 : 0;
    scan_kernel<<<BB, 512, smemScan>>>(h0, Whw, Whb, out, hasFinal);
}

// round 4
// speedup vs baseline: 1.2445x; 1.2445x over previous
#include <cuda_runtime.h>
#include <cuda_bf16.h>
#include <math.h>
#include <stdint.h>

#define LL 1024
#define BB 128
#define DD 256
#define HH 256

// ====================================================================
// xproj GEMM via portable mma.sync (bf16 split-3, fp32 accum)
//   C[m,n] = sum_k X[m,k] * Wx[n,k] + bx[n]
//   CTA tile 128x128, 8 warps (4M x 2N), warp tile 32x64, K-chunk 64.
// ====================================================================

// smem layout (bytes): padded bf16 tiles, row stride 72 halves (144 B)
#define XP_STRIDE_H 72
#define XP_STRIDE_B 144
#define XP_TILE_B   (128 * XP_STRIDE_B)   // 18432
#define XP_AHI 0
#define XP_ALO XP_TILE_B
#define XP_WHI (2 * XP_TILE_B)
#define XP_WLO (3 * XP_TILE_B)
#define XP_SMEM (4 * XP_TILE_B)           // 73728

__device__ __forceinline__ uint32_t smem_u32(const void* p) {
    uint32_t a;
    asm("{ .reg .u64 t; cvta.to.shared.u64 t, %1; cvt.u32.u64 %0, t; }"
        : "=r"(a) : "l"(p));
    return a;
}

__device__ __forceinline__ void ldm_x4(uint32_t& r0, uint32_t& r1,
                                       uint32_t& r2, uint32_t& r3, uint32_t addr) {
    asm volatile("ldmatrix.sync.aligned.m8n8.x4.shared.b16 {%0,%1,%2,%3}, [%4];"
                 : "=r"(r0), "=r"(r1), "=r"(r2), "=r"(r3) : "r"(addr));
}

__device__ __forceinline__ void mma16816(float* c, const uint32_t* a,
                                         uint32_t b0, uint32_t b1) {
    asm volatile(
        "mma.sync.aligned.m16n8k16.row.col.f32.bf16.bf16.f32 "
        "{%0,%1,%2,%3}, {%4,%5,%6,%7}, {%8,%9}, {%0,%1,%2,%3};"
        : "+f"(c[0]), "+f"(c[1]), "+f"(c[2]), "+f"(c[3])
        : "r"(a[0]), "r"(a[1]), "r"(a[2]), "r"(a[3]), "r"(b0), "r"(b1));
}

__device__ __forceinline__ void split2(float a, float b, uint32_t& h, uint32_t& l) {
    __nv_bfloat16 ha = __float2bfloat16(a);
    __nv_bfloat16 hb = __float2bfloat16(b);
    float ra = a - __bfloat162float(ha);
    float rb = b - __bfloat162float(hb);
    __nv_bfloat16 la = __float2bfloat16(ra);
    __nv_bfloat16 lb = __float2bfloat16(rb);
    h = (uint32_t)reinterpret_cast<unsigned short&>(ha) |
        ((uint32_t)reinterpret_cast<unsigned short&>(hb) << 16);
    l = (uint32_t)reinterpret_cast<unsigned short&>(la) |
        ((uint32_t)reinterpret_cast<unsigned short&>(lb) << 16);
}

__global__ __launch_bounds__(256) void xproj_mma_kernel(
    const float* __restrict__ X,
    const float* __restrict__ Wx,
    const float* __restrict__ bx,
    float* __restrict__ C)
{
    extern __shared__ char smem[];
    const uint32_t sb = smem_u32(smem);
    const int tid = threadIdx.x;
    const int wid = tid >> 5;
    const int l   = tid & 31;
    const int warp_m = wid & 3;      // 0..3, 32 rows each
    const int warp_n = wid >> 2;     // 0..1, 64 cols each
    const int m0 = blockIdx.x * 128;
    const int n0 = blockIdx.y * 128;

    float acc[2][8][4];
#pragma unroll
    for (int t = 0; t < 2; t++)
#pragma unroll
        for (int nb = 0; nb < 8; nb++)
#pragma unroll
            for (int i = 0; i < 4; i++) acc[t][nb][i] = 0.0f;

    // per-lane ldmatrix base offsets (bytes, within a tile)
    const uint32_t aRowOff = (uint32_t)((warp_m * 32 + (l & 15)) * XP_STRIDE_B +
                                        (l >> 4) * 16);
    const uint32_t bRowOff = (uint32_t)((warp_n * 64 + ((l >> 4) << 3) + (l & 7)) * XP_STRIDE_B +
                                        ((l >> 3) & 1) * 16);

    for (int c = 0; c < 4; ++c) {
        const int k0 = c * 64;

        // --- convert+stage A: 128 rows x 64 k (1024 jobs of 8 floats) ---
#pragma unroll
        for (int q = 0; q < 4; ++q) {
            int job = q * 256 + tid;
            int row = job >> 3, kg = job & 7;
            const float4* s = (const float4*)(X + (size_t)(m0 + row) * DD + k0 + kg * 8);
            float4 v0 = s[0], v1 = s[1];
            uint4 hi, lo;
            split2(v0.x, v0.y, hi.x, lo.x);
            split2(v0.z, v0.w, hi.y, lo.y);
            split2(v1.x, v1.y, hi.z, lo.z);
            split2(v1.z, v1.w, hi.w, lo.w);
            int off = row * XP_STRIDE_B + kg * 16;
            *(uint4*)(smem + XP_AHI + off) = hi;
            *(uint4*)(smem + XP_ALO + off) = lo;
        }
        // --- convert+stage W: 128 rows x 64 k ---
#pragma unroll
        for (int q = 0; q < 4; ++q) {
            int job = q * 256 + tid;
            int row = job >> 3, kg = job & 7;
            const float4* s = (const float4*)(Wx + (size_t)(n0 + row) * DD + k0 + kg * 8);
            float4 v0 = s[0], v1 = s[1];
            uint4 hi, lo;
            split2(v0.x, v0.y, hi.x, lo.x);
            split2(v0.z, v0.w, hi.y, lo.y);
            split2(v1.x, v1.y, hi.z, lo.z);
            split2(v1.z, v1.w, hi.w, lo.w);
            int off = row * XP_STRIDE_B + kg * 16;
            *(uint4*)(smem + XP_WHI + off) = hi;
            *(uint4*)(smem + XP_WLO + off) = lo;
        }
        __syncthreads();

#pragma unroll
        for (int ks = 0; ks < 4; ++ks) {
            const uint32_t kOff = (uint32_t)(ks * 32);
            uint32_t ahi[2][4], alo[2][4];
#pragma unroll
            for (int t = 0; t < 2; t++) {
                uint32_t abase = aRowOff + (uint32_t)(t * 16 * XP_STRIDE_B) + kOff;
                ldm_x4(ahi[t][0], ahi[t][1], ahi[t][2], ahi[t][3], sb + XP_AHI + abase);
                ldm_x4(alo[t][0], alo[t][1], alo[t][2], alo[t][3], sb + XP_ALO + abase);
            }
#pragma unroll
            for (int g = 0; g < 4; ++g) {   // g covers 2 n-blocks of 8
                uint32_t bbase = bRowOff + (uint32_t)(g * 16 * XP_STRIDE_B) + kOff;
                uint32_t h0, h1, h2, h3, q0, q1, q2, q3;
                ldm_x4(h0, h1, h2, h3, sb + XP_WHI + bbase);
                ldm_x4(q0, q1, q2, q3, sb + XP_WLO + bbase);
#pragma unroll
                for (int t = 0; t < 2; t++) {
                    mma16816(acc[t][2 * g],     ahi[t], h0, h1);
                    mma16816(acc[t][2 * g + 1], ahi[t], h2, h3);
                    mma16816(acc[t][2 * g],     alo[t], h0, h1);
                    mma16816(acc[t][2 * g + 1], alo[t], h2, h3);
                    mma16816(acc[t][2 * g],     ahi[t], q0, q1);
                    mma16816(acc[t][2 * g + 1], ahi[t], q2, q3);
                }
            }
        }
        __syncthreads();
    }

    // --- epilogue: d fragment (t/4 = row, 2*(t%4) = col pair) ---
    const int mrow = m0 + warp_m * 32 + (l >> 2);
    const int ncol = n0 + warp_n * 64 + 2 * (l & 3);
#pragma unroll
    for (int t = 0; t < 2; t++) {
#pragma unroll
        for (int nb = 0; nb < 8; nb++) {
            int nn = ncol + nb * 8;
            float2 bv = *(const float2*)(bx + nn);
            int r0 = mrow + t * 16;
            float2 o0 = make_float2(acc[t][nb][0] + bv.x, acc[t][nb][1] + bv.y);
            float2 o1 = make_float2(acc[t][nb][2] + bv.x, acc[t][nb][3] + bv.y);
            *(float2*)(C + (size_t)r0 * HH + nn) = o0;
            *(float2*)(C + (size_t)(r0 + 8) * HH + nn) = o1;
        }
    }
}

// ====================================================================
// Kernel 2: persistent scan. One CTA per batch element (128 CTAs).
// 512 threads: (j = tid&255, half = tid>>8), k in [half*128, ...+128).
// 96 k-weights in registers (24 float4), 32 in smem (64 KB total).
// ====================================================================
__global__ __launch_bounds__(512, 1) void scan_kernel(
    const float* __restrict__ h0,
    const float* __restrict__ Wh,
    const float* __restrict__ bh,
    float* __restrict__ out,
    int hasFinal)
{
    extern __shared__ float smemf[];
    float4* Ws4  = (float4*)smemf;           // 16*256 float4 = 64 KB
    float*  hbuf = smemf + 16 * 256 * 4;     // 2*256 floats (ping-pong)
    float*  part = hbuf + 512;               // 256 floats
    float*  bh_s = part + 256;               // 256 floats

    const int tid  = threadIdx.x;
    const int j    = tid & 255;
    const int half = tid >> 8;
    const int b    = blockIdx.x;
    const int kb   = half * 128;

    // register-resident weights: k in [kb, kb+96)
    float4 wr[24];
    const float4* wrow = (const float4*)(Wh + (size_t)j * HH + kb);
#pragma unroll
    for (int i = 0; i < 24; i++) wr[i] = wrow[i];

    // shared weights: g<8 -> k = 96+4g (half 0), g>=8 -> k = 224+4(g-8) (half 1)
    for (int idx = tid; idx < 16 * 256; idx += 512) {
        int g  = idx >> 8;
        int jj = idx & 255;
        int kk = (g < 8) ? (96 + 4 * g) : (224 + 4 * (g - 8));
        Ws4[g * 256 + jj] = *(const float4*)(Wh + (size_t)jj * HH + kk);
    }
    if (tid < 256) {
        hbuf[tid] = h0[(size_t)b * HH + tid];
        bh_s[tid] = bh[tid];
    }
    __syncthreads();

    int cur = 0;
    for (int t = 0; t < LL; ++t) {
        float xp = 0.0f;
        if (!half) xp = out[(size_t)t * (BB * HH) + (size_t)b * HH + j];

        const float4* h4 = (const float4*)(hbuf + cur * 256 + kb);
        float a0 = 0.f, a1 = 0.f, a2 = 0.f, a3 = 0.f;
#pragma unroll
        for (int i = 0; i < 24; i++) {
            float4 hv = h4[i];
            a0 = fmaf(wr[i].x, hv.x, a0);
            a1 = fmaf(wr[i].y, hv.y, a1);
            a2 = fmaf(wr[i].z, hv.z, a2);
            a3 = fmaf(wr[i].w, hv.w, a3);
        }
        const float4* wsp = Ws4 + half * 8 * 256 + j;
#pragma unroll
        for (int g = 0; g < 8; g++) {
            float4 wv = wsp[g * 256];
            float4 hv = h4[24 + g];
            a0 = fmaf(wv.x, hv.x, a0);
            a1 = fmaf(wv.y, hv.y, a1);
            a2 = fmaf(wv.z, hv.z, a2);
            a3 = fmaf(wv.w, hv.w, a3);
        }
        float acc = (a0 + a1) + (a2 + a3);

        if (half) part[j] = acc;
        __syncthreads();

        if (!half) {
            float v  = acc + part[j] + xp + bh_s[j];
            float hn = tanhf(v);
            hbuf[(cur ^ 1) * 256 + j] = hn;
            out[(size_t)t * (BB * HH) + (size_t)b * HH + j] = hn;
            if (hasFinal && t == LL - 1)
                out[(size_t)LL * BB * HH + (size_t)b * HH + j] = hn;
        }
        __syncthreads();
        cur ^= 1;
    }
}

// ====================================================================
// launch
// ====================================================================
extern "C" void kernel_launch(void* const* d_in, const int* in_sizes, int n_in,
                              void* d_out, int out_size)
{
    const float* x   = (const float*)d_in[0];  // [L,B,D]
    const float* h0  = (const float*)d_in[1];  // [B,H]
    const float* Wxw = (const float*)d_in[2];  // [H,D]
    const float* Wxb = (const float*)d_in[3];  // [H]
    const float* Whw = (const float*)d_in[4];  // [H,H]
    const float* Whb = (const float*)d_in[5];  // [H]
    float* out = (float*)d_out;

    (void)in_sizes; (void)n_in;

    cudaFuncSetAttribute(xproj_mma_kernel, cudaFuncAttributeMaxDynamicSharedMemorySize, XP_SMEM);
    const int smemScan = (16 * 256 * 4 + 512 + 256 + 256) * (int)sizeof(float); // 69632
    cudaFuncSetAttribute(scan_kernel, cudaFuncAttributeMaxDynamicSharedMemorySize, smemScan);

    dim3 g1(LL * BB / 128, HH / 128);   // (1024, 2)
    xproj_mma_kernel<<<g1, 256, XP_SMEM>>>(x, Wxw, Wxb, out);

    const int hasFinal = (out_size >= LL * BB * HH + BB * HH) ? 1 : 0;
    scan_kernel<<<BB, 512, smemScan>>>(h0, Whw, Whb, out, hasFinal);
}

// round 5
// speedup vs baseline: 1.2456x; 1.0008x over previous
#include <cuda_runtime.h>
#include <cuda_bf16.h>
#include <math.h>
#include <stdint.h>

#define LL 1024
#define BB 128
#define DD 256
#define HH 256

#define XN (LL * BB * DD)     // 33554432 X elements
#define WN (HH * DD)          // 65536 Wx elements

// Pre-split bf16 scratch (static device arrays — allowed)
__device__ __align__(16) __nv_bfloat16 g_xhi[XN];
__device__ __align__(16) __nv_bfloat16 g_xlo[XN];
__device__ __align__(16) __nv_bfloat16 g_whi[WN];
__device__ __align__(16) __nv_bfloat16 g_wlo[WN];

__device__ __forceinline__ uint32_t smem_u32(const void* p) {
    uint32_t a;
    asm("{ .reg .u64 t; cvta.to.shared.u64 t, %1; cvt.u32.u64 %0, t; }"
        : "=r"(a) : "l"(p));
    return a;
}

__device__ __forceinline__ void split2(float a, float b, uint32_t& h, uint32_t& l) {
    __nv_bfloat16 ha = __float2bfloat16(a);
    __nv_bfloat16 hb = __float2bfloat16(b);
    float ra = a - __bfloat162float(ha);
    float rb = b - __bfloat162float(hb);
    __nv_bfloat16 la = __float2bfloat16(ra);
    __nv_bfloat16 lb = __float2bfloat16(rb);
    h = (uint32_t)reinterpret_cast<unsigned short&>(ha) |
        ((uint32_t)reinterpret_cast<unsigned short&>(hb) << 16);
    l = (uint32_t)reinterpret_cast<unsigned short&>(la) |
        ((uint32_t)reinterpret_cast<unsigned short&>(lb) << 16);
}

// ====================================================================
// Kernel 0: one-shot fp32 -> split-bf16 (hi, lo) for X and Wx.
// 4 floats per thread; bandwidth bound.
// ====================================================================
#define CV_JOBS ((XN + WN) / 4)    // 8420352... (XN/4=8388608, WN/4=16384) = 8404992

__global__ __launch_bounds__(256) void convert_kernel(
    const float* __restrict__ X, const float* __restrict__ Wx)
{
    int i = blockIdx.x * 256 + threadIdx.x;
    if (i >= CV_JOBS) return;
    float4 v;
    if (i < XN / 4) v = ((const float4*)X)[i];
    else            v = ((const float4*)Wx)[i - XN / 4];
    uint2 hi, lo;
    split2(v.x, v.y, hi.x, lo.x);
    split2(v.z, v.w, hi.y, lo.y);
    if (i < XN / 4) {
        *(uint2*)(g_xhi + (size_t)i * 4) = hi;
        *(uint2*)(g_xlo + (size_t)i * 4) = lo;
    } else {
        size_t o = (size_t)(i - XN / 4) * 4;
        *(uint2*)(g_whi + o) = hi;
        *(uint2*)(g_wlo + o) = lo;
    }
}

// ====================================================================
// Kernel 1: xproj GEMM via mma.sync bf16 split-3, fp32 accum.
//   C[m,n] = Xhi*Whi^T + Xlo*Whi^T + Xhi*Wlo^T + bx
//   CTA tile 128x128, 8 warps (4M x 2N), warp tile 32x64, K-chunk 64.
// ====================================================================
#define XP_STRIDE_B 144                  // 72 halves per row (padded)
#define XP_TILE_B   (128 * XP_STRIDE_B)  // 18432
#define XP_AHI 0
#define XP_ALO XP_TILE_B
#define XP_WHI (2 * XP_TILE_B)
#define XP_WLO (3 * XP_TILE_B)
#define XP_SMEM (4 * XP_TILE_B)          // 73728

__device__ __forceinline__ void ldm_x4(uint32_t& r0, uint32_t& r1,
                                       uint32_t& r2, uint32_t& r3, uint32_t addr) {
    asm volatile("ldmatrix.sync.aligned.m8n8.x4.shared.b16 {%0,%1,%2,%3}, [%4];"
                 : "=r"(r0), "=r"(r1), "=r"(r2), "=r"(r3) : "r"(addr));
}

__device__ __forceinline__ void mma16816(float* c, const uint32_t* a,
                                         uint32_t b0, uint32_t b1) {
    asm volatile(
        "mma.sync.aligned.m16n8k16.row.col.f32.bf16.bf16.f32 "
        "{%0,%1,%2,%3}, {%4,%5,%6,%7}, {%8,%9}, {%0,%1,%2,%3};"
        : "+f"(c[0]), "+f"(c[1]), "+f"(c[2]), "+f"(c[3])
        : "r"(a[0]), "r"(a[1]), "r"(a[2]), "r"(a[3]), "r"(b0), "r"(b1));
}

__global__ __launch_bounds__(256) void xproj_mma_kernel(
    const float* __restrict__ bx,
    float* __restrict__ C)
{
    extern __shared__ char smem[];
    const uint32_t sb = smem_u32(smem);
    const int tid = threadIdx.x;
    const int wid = tid >> 5;
    const int l   = tid & 31;
    const int warp_m = wid & 3;
    const int warp_n = wid >> 2;
    const int m0 = blockIdx.x * 128;
    const int n0 = blockIdx.y * 128;

    float acc[2][8][4];
#pragma unroll
    for (int t = 0; t < 2; t++)
#pragma unroll
        for (int nb = 0; nb < 8; nb++)
#pragma unroll
            for (int i = 0; i < 4; i++) acc[t][nb][i] = 0.0f;

    const uint32_t aRowOff = (uint32_t)((warp_m * 32 + (l & 15)) * XP_STRIDE_B +
                                        (l >> 4) * 16);
    const uint32_t bRowOff = (uint32_t)((warp_n * 64 + ((l >> 4) << 3) + (l & 7)) * XP_STRIDE_B +
                                        ((l >> 3) & 1) * 16);

    for (int c = 0; c < 4; ++c) {
        const int k0 = c * 64;

        // stage A hi/lo: 128 rows x 64 halves = 1024 uint4, 4 jobs/thread
#pragma unroll
        for (int q = 0; q < 4; ++q) {
            int job = q * 256 + tid;
            int row = job >> 3, kg = job & 7;
            size_t src = (size_t)(m0 + row) * DD + k0 + kg * 8;
            int off = row * XP_STRIDE_B + kg * 16;
            *(uint4*)(smem + XP_AHI + off) = *(const uint4*)(g_xhi + src);
            *(uint4*)(smem + XP_ALO + off) = *(const uint4*)(g_xlo + src);
        }
        // stage W hi/lo
#pragma unroll
        for (int q = 0; q < 4; ++q) {
            int job = q * 256 + tid;
            int row = job >> 3, kg = job & 7;
            size_t src = (size_t)(n0 + row) * DD + k0 + kg * 8;
            int off = row * XP_STRIDE_B + kg * 16;
            *(uint4*)(smem + XP_WHI + off) = *(const uint4*)(g_whi + src);
            *(uint4*)(smem + XP_WLO + off) = *(const uint4*)(g_wlo + src);
        }
        __syncthreads();

#pragma unroll
        for (int ks = 0; ks < 4; ++ks) {
            const uint32_t kOff = (uint32_t)(ks * 32);
            uint32_t ahi[2][4], alo[2][4];
#pragma unroll
            for (int t = 0; t < 2; t++) {
                uint32_t abase = aRowOff + (uint32_t)(t * 16 * XP_STRIDE_B) + kOff;
                ldm_x4(ahi[t][0], ahi[t][1], ahi[t][2], ahi[t][3], sb + XP_AHI + abase);
                ldm_x4(alo[t][0], alo[t][1], alo[t][2], alo[t][3], sb + XP_ALO + abase);
            }
#pragma unroll
            for (int g = 0; g < 4; ++g) {
                uint32_t bbase = bRowOff + (uint32_t)(g * 16 * XP_STRIDE_B) + kOff;
                uint32_t h0, h1, h2, h3, q0, q1, q2, q3;
                ldm_x4(h0, h1, h2, h3, sb + XP_WHI + bbase);
                ldm_x4(q0, q1, q2, q3, sb + XP_WLO + bbase);
#pragma unroll
                for (int t = 0; t < 2; t++) {
                    mma16816(acc[t][2 * g],     ahi[t], h0, h1);
                    mma16816(acc[t][2 * g + 1], ahi[t], h2, h3);
                    mma16816(acc[t][2 * g],     alo[t], h0, h1);
                    mma16816(acc[t][2 * g + 1], alo[t], h2, h3);
                    mma16816(acc[t][2 * g],     ahi[t], q0, q1);
                    mma16816(acc[t][2 * g + 1], ahi[t], q2, q3);
                }
            }
        }
        __syncthreads();
    }

    const int mrow = m0 + warp_m * 32 + (l >> 2);
    const int ncol = n0 + warp_n * 64 + 2 * (l & 3);
#pragma unroll
    for (int t = 0; t < 2; t++) {
#pragma unroll
        for (int nb = 0; nb < 8; nb++) {
            int nn = ncol + nb * 8;
            float2 bv = *(const float2*)(bx + nn);
            int r0 = mrow + t * 16;
            float2 o0 = make_float2(acc[t][nb][0] + bv.x, acc[t][nb][1] + bv.y);
            float2 o1 = make_float2(acc[t][nb][2] + bv.x, acc[t][nb][3] + bv.y);
            *(float2*)(C + (size_t)r0 * HH + nn) = o0;
            *(float2*)(C + (size_t)(r0 + 8) * HH + nn) = o1;
        }
    }
}

// ====================================================================
// Kernel 2: persistent scan (unchanged — at crossbar/FFMA dual floor).
// ====================================================================
__global__ __launch_bounds__(512, 1) void scan_kernel(
    const float* __restrict__ h0,
    const float* __restrict__ Wh,
    const float* __restrict__ bh,
    float* __restrict__ out,
    int hasFinal)
{
    extern __shared__ float smemf[];
    float4* Ws4  = (float4*)smemf;           // 16*256 float4 = 64 KB
    float*  hbuf = smemf + 16 * 256 * 4;
    float*  part = hbuf + 512;
    float*  bh_s = part + 256;

    const int tid  = threadIdx.x;
    const int j    = tid & 255;
    const int half = tid >> 8;
    const int b    = blockIdx.x;
    const int kb   = half * 128;

    float4 wr[24];
    const float4* wrow = (const float4*)(Wh + (size_t)j * HH + kb);
#pragma unroll
    for (int i = 0; i < 24; i++) wr[i] = wrow[i];

    for (int idx = tid; idx < 16 * 256; idx += 512) {
        int g  = idx >> 8;
        int jj = idx & 255;
        int kk = (g < 8) ? (96 + 4 * g) : (224 + 4 * (g - 8));
        Ws4[g * 256 + jj] = *(const float4*)(Wh + (size_t)jj * HH + kk);
    }
    if (tid < 256) {
        hbuf[tid] = h0[(size_t)b * HH + tid];
        bh_s[tid] = bh[tid];
    }
    __syncthreads();

    int cur = 0;
    for (int t = 0; t < LL; ++t) {
        float xp = 0.0f;
        if (!half) xp = out[(size_t)t * (BB * HH) + (size_t)b * HH + j];

        const float4* h4 = (const float4*)(hbuf + cur * 256 + kb);
        float a0 = 0.f, a1 = 0.f, a2 = 0.f, a3 = 0.f;
#pragma unroll
        for (int i = 0; i < 24; i++) {
            float4 hv = h4[i];
            a0 = fmaf(wr[i].x, hv.x, a0);
            a1 = fmaf(wr[i].y, hv.y, a1);
            a2 = fmaf(wr[i].z, hv.z, a2);
            a3 = fmaf(wr[i].w, hv.w, a3);
        }
        const float4* wsp = Ws4 + half * 8 * 256 + j;
#pragma unroll
        for (int g = 0; g < 8; g++) {
            float4 wv = wsp[g * 256];
            float4 hv = h4[24 + g];
            a0 = fmaf(wv.x, hv.x, a0);
            a1 = fmaf(wv.y, hv.y, a1);
            a2 = fmaf(wv.z, hv.z, a2);
            a3 = fmaf(wv.w, hv.w, a3);
        }
        float acc = (a0 + a1) + (a2 + a3);

        if (half) part[j] = acc;
        __syncthreads();

        if (!half) {
            float v  = acc + part[j] + xp + bh_s[j];
            float hn = tanhf(v);
            hbuf[(cur ^ 1) * 256 + j] = hn;
            out[(size_t)t * (BB * HH) + (size_t)b * HH + j] = hn;
            if (hasFinal && t == LL - 1)
                out[(size_t)LL * BB * HH + (size_t)b * HH + j] = hn;
        }
        __syncthreads();
        cur ^= 1;
    }
}

// ====================================================================
// launch
// ====================================================================
extern "C" void kernel_launch(void* const* d_in, const int* in_sizes, int n_in,
                              void* d_out, int out_size)
{
    const float* x   = (const float*)d_in[0];
    const float* h0  = (const float*)d_in[1];
    const float* Wxw = (const float*)d_in[2];
    const float* Wxb = (const float*)d_in[3];
    const float* Whw = (const float*)d_in[4];
    const float* Whb = (const float*)d_in[5];
    float* out = (float*)d_out;

    (void)in_sizes; (void)n_in;

    cudaFuncSetAttribute(xproj_mma_kernel, cudaFuncAttributeMaxDynamicSharedMemorySize, XP_SMEM);
    const int smemScan = (16 * 256 * 4 + 512 + 256 + 256) * (int)sizeof(float);
    cudaFuncSetAttribute(scan_kernel, cudaFuncAttributeMaxDynamicSharedMemorySize, smemScan);

    convert_kernel<<<(CV_JOBS + 255) / 256, 256>>>(x, Wxw);

    dim3 g1(LL * BB / 128, HH / 128);   // (1024, 2)
    xproj_mma_kernel<<<g1, 256, XP_SMEM>>>(Wxb, out);

    const int hasFinal = (out_size >= LL * BB * HH + BB * HH) ? 1 : 0;
    scan_kernel<<<BB, 512, smemScan>>>(h0, Whw, Whb, out, hasFinal);
}